// round 3
// baseline (speedup 1.0000x reference)
#include <cuda_runtime.h>

// HN=10, ND=40, HF=8, STRIDE=3, ESTRIDE=3 (fixed by reference)
// A_ENC: agg[j] = sum x[4j-3 .. 4j+2 mod 40]
// A_PRED: agg2[d] = z1[d] + w*(z1[d-1]+z1[d+1]), w = exp(-1/9)
// A_DEC per grid i (m=i%4): m0:s[c]; m1:s[c]+s[c+1]; m2:s[c]+s[c+1]; m3:s[c+1]  (c=i/4, wrap mod 10)

typedef unsigned long long u64;

__device__ __forceinline__ u64 pk2(float a, float b) {
    u64 r; asm("mov.b64 %0, {%1, %2};" : "=l"(r) : "f"(a), "f"(b)); return r;
}
__device__ __forceinline__ void upk2(u64 v, float& a, float& b) {
    asm("mov.b64 {%0, %1}, %2;" : "=f"(a), "=f"(b) : "l"(v));
}
__device__ __forceinline__ u64 ffma2(u64 a, u64 b, u64 c) {
    u64 d; asm("fma.rn.f32x2 %0, %1, %2, %3;" : "=l"(d) : "l"(a), "l"(b), "l"(c)); return d;
}

// Packed weights written by prep_kernel (deterministic each launch)
__device__ u64 g_encW[8][4];   // [g][f2] = (enc_root_w[2f2][g], enc_root_w[2f2+1][g])
__device__ u64 g_encRW[4];     // enc_rel_w pairs
__device__ u64 g_encB[4];      // enc_rel_b pairs
__device__ u64 g_W1[8][4];     // (pred_rel_w + pred_root_w) pairs
__device__ u64 g_W2[8][4];     // (exp(-1/9) * pred_rel_w) pairs
__device__ u64 g_predB[4];     // pred_rel_b pairs
__device__ float g_drw[8];     // dec_rel_w
__device__ float g_dec2[2];    // dec_rel_b, dec_root_w

__global__ void prep_kernel(const float* __restrict__ erw, const float* __restrict__ erb,
                            const float* __restrict__ erow,
                            const float* __restrict__ prw, const float* __restrict__ prb,
                            const float* __restrict__ prow,
                            const float* __restrict__ drw, const float* __restrict__ drb,
                            const float* __restrict__ droot) {
    const int t = threadIdx.x;
    const float wE = expf(-1.0f / 9.0f);
    if (t < 32) {
        const int g = t & 7, f2 = t >> 3;
        const int i0 = (2 * f2) * 8 + g;
        const int i1 = (2 * f2 + 1) * 8 + g;
        g_encW[g][f2] = pk2(erow[i0], erow[i1]);
        g_W1[g][f2]   = pk2(prw[i0] + prow[i0], prw[i1] + prow[i1]);
        g_W2[g][f2]   = pk2(wE * prw[i0], wE * prw[i1]);
    }
    if (t < 4) {
        g_encRW[t] = pk2(erw[2 * t], erw[2 * t + 1]);
        g_encB[t]  = pk2(erb[2 * t], erb[2 * t + 1]);
        g_predB[t] = pk2(prb[2 * t], prb[2 * t + 1]);
    }
    if (t < 8) g_drw[t] = drw[t];
    if (t == 0) { g_dec2[0] = drb[0]; g_dec2[1] = droot[0]; }
}

// Shared: buf float4[128*21] (z/z1, also x transiently as [128][11]) = 43008B
//         ss float[128*11] = 5632B.  Total 48640B -> 4 blocks/SM.
#define ZROW 21
#define SMEM_BYTES (128 * ZROW * 16 + 128 * 11 * 4)

__global__ __launch_bounds__(128, 4)
void gnn_kernel(const float* __restrict__ x, const float* __restrict__ z,
                const float* __restrict__ y, float* __restrict__ out) {
    extern __shared__ float4 sm4[];
    float4* buf  = sm4;
    float*  bufF = (float*)sm4;
    float*  ss   = (float*)(sm4 + 128 * ZROW);

    const int t = threadIdx.x;
    const long long blk = blockIdx.x;

    // ---- Phase 1: stage x coalesced into [128][11] float4 ----
    const float4* xg = (const float4*)x + blk * 1280;
#pragma unroll
    for (int k = 0; k < 10; k++) {
        const int i4 = t + k * 128;
        buf[(i4 / 10) * 11 + (i4 % 10)] = xg[i4];
    }
    __syncthreads();

    // ---- Phase 2: encoder aggregation into registers ----
    float xv[40];
#pragma unroll
    for (int c = 0; c < 10; c++) {
        const float4 v = buf[t * 11 + c];
        xv[4 * c] = v.x; xv[4 * c + 1] = v.y; xv[4 * c + 2] = v.z; xv[4 * c + 3] = v.w;
    }
    float agg[10];
#pragma unroll
    for (int j = 0; j < 10; j++) {
        float s0 = 0.0f;
#pragma unroll
        for (int kk = 0; kk < 6; kk++) s0 += xv[(4 * j - 3 + kk + 40) % 40];
        agg[j] = s0;
    }
    __syncthreads();   // x reads done before z overwrites buf

    // ---- Phase 3: stage z coalesced into [128][21] float4 with XOR swizzle ----
    // element row e, logical chunk c stored at slot c ^ ((e>>3)&3): makes the
    // later fixed-(j,g) scalar accesses bank-conflict-free across the warp.
    const float4* zg = (const float4*)z + blk * 2560;
#pragma unroll
    for (int k = 0; k < 20; k++) {
        const int i4 = t + k * 128;
        const int e = i4 / 20, c = i4 % 20;
        buf[e * ZROW + (c ^ ((e >> 3) & 3))] = zg[i4];
    }
    __syncthreads();

    const int sw   = (t >> 3) & 3;
    const int rowF = t * (ZROW * 4);   // float index of own row

    // ---- Stage A: z1[j][f] = relu(agg[j]*erw[f] + erb[f] + sum_g z[j][g]*erow[f][g]) ----
    u64 acc[40];
    {
        const u64 rw0 = g_encRW[0], rw1 = g_encRW[1], rw2 = g_encRW[2], rw3 = g_encRW[3];
        const u64 b0 = g_encB[0], b1 = g_encB[1], b2 = g_encB[2], b3 = g_encB[3];
#pragma unroll
        for (int j = 0; j < 10; j++) {
            const u64 ab = pk2(agg[j], agg[j]);
            acc[j * 4 + 0] = ffma2(ab, rw0, b0);
            acc[j * 4 + 1] = ffma2(ab, rw1, b1);
            acc[j * 4 + 2] = ffma2(ab, rw2, b2);
            acc[j * 4 + 3] = ffma2(ab, rw3, b3);
        }
    }
#pragma unroll 1
    for (int g = 0; g < 8; g++) {
        const u64 w0 = g_encW[g][0], w1 = g_encW[g][1], w2 = g_encW[g][2], w3 = g_encW[g][3];
        const int gh = g >> 2, gw = g & 3;
#pragma unroll
        for (int j = 0; j < 10; j++) {
            const float zv = bufF[rowF + (((2 * j + gh) ^ sw) << 2) + gw];
            const u64 zb = pk2(zv, zv);
            acc[j * 4 + 0] = ffma2(zb, w0, acc[j * 4 + 0]);
            acc[j * 4 + 1] = ffma2(zb, w1, acc[j * 4 + 1]);
            acc[j * 4 + 2] = ffma2(zb, w2, acc[j * 4 + 2]);
            acc[j * 4 + 3] = ffma2(zb, w3, acc[j * 4 + 3]);
        }
    }
    // relu + write z1 back in place (own row only -> no sync needed)
#pragma unroll
    for (int j = 0; j < 10; j++) {
        float f0, f1, f2v, f3, f4v, f5, f6, f7;
        upk2(acc[j * 4 + 0], f0, f1);
        upk2(acc[j * 4 + 1], f2v, f3);
        upk2(acc[j * 4 + 2], f4v, f5);
        upk2(acc[j * 4 + 3], f6, f7);
        float4 lo, hi;
        lo.x = fmaxf(f0, 0.0f);  lo.y = fmaxf(f1, 0.0f);
        lo.z = fmaxf(f2v, 0.0f); lo.w = fmaxf(f3, 0.0f);
        hi.x = fmaxf(f4v, 0.0f); hi.y = fmaxf(f5, 0.0f);
        hi.z = fmaxf(f6, 0.0f);  hi.w = fmaxf(f7, 0.0f);
        buf[t * ZROW + ((2 * j) ^ sw)]     = lo;
        buf[t * ZROW + ((2 * j + 1) ^ sw)] = hi;
    }

    // ---- Stage B: z2[d] = relu(z1[d]@W1^T + (z1[d-1]+z1[d+1])@W2^T + prb); s[d]=z2[d].drw ----
    {
        const u64 pb0 = g_predB[0], pb1 = g_predB[1], pb2 = g_predB[2], pb3 = g_predB[3];
#pragma unroll
        for (int d = 0; d < 10; d++) {
            acc[d * 4 + 0] = pb0; acc[d * 4 + 1] = pb1;
            acc[d * 4 + 2] = pb2; acc[d * 4 + 3] = pb3;
        }
    }
#pragma unroll 1
    for (int g = 0; g < 8; g++) {
        const u64 a0 = g_W1[g][0], a1 = g_W1[g][1], a2 = g_W1[g][2], a3 = g_W1[g][3];
        const u64 c0 = g_W2[g][0], c1 = g_W2[g][1], c2 = g_W2[g][2], c3 = g_W2[g][3];
        const int gh = g >> 2, gw = g & 3;
        float z1g[10];
#pragma unroll
        for (int j = 0; j < 10; j++)
            z1g[j] = bufF[rowF + (((2 * j + gh) ^ sw) << 2) + gw];
#pragma unroll
        for (int d = 0; d < 10; d++) {
            const int dm = (d == 0) ? 9 : d - 1;
            const int dp = (d == 9) ? 0 : d + 1;
            const float u = z1g[dm] + z1g[dp];
            const u64 zb = pk2(z1g[d], z1g[d]);
            const u64 ub = pk2(u, u);
            acc[d * 4 + 0] = ffma2(zb, a0, acc[d * 4 + 0]);
            acc[d * 4 + 1] = ffma2(zb, a1, acc[d * 4 + 1]);
            acc[d * 4 + 2] = ffma2(zb, a2, acc[d * 4 + 2]);
            acc[d * 4 + 3] = ffma2(zb, a3, acc[d * 4 + 3]);
            acc[d * 4 + 0] = ffma2(ub, c0, acc[d * 4 + 0]);
            acc[d * 4 + 1] = ffma2(ub, c1, acc[d * 4 + 1]);
            acc[d * 4 + 2] = ffma2(ub, c2, acc[d * 4 + 2]);
            acc[d * 4 + 3] = ffma2(ub, c3, acc[d * 4 + 3]);
        }
    }
    // relu + dot with dec_rel_w -> s[d]
    {
        const float d0 = g_drw[0], d1 = g_drw[1], d2 = g_drw[2], d3 = g_drw[3];
        const float d4 = g_drw[4], d5 = g_drw[5], d6 = g_drw[6], d7 = g_drw[7];
#pragma unroll
        for (int d = 0; d < 10; d++) {
            float f0, f1, f2v, f3, f4v, f5, f6, f7;
            upk2(acc[d * 4 + 0], f0, f1);
            upk2(acc[d * 4 + 1], f2v, f3);
            upk2(acc[d * 4 + 2], f4v, f5);
            upk2(acc[d * 4 + 3], f6, f7);
            float sd = fmaxf(f0, 0.0f) * d0 + fmaxf(f1, 0.0f) * d1
                     + fmaxf(f2v, 0.0f) * d2 + fmaxf(f3, 0.0f) * d3
                     + fmaxf(f4v, 0.0f) * d4 + fmaxf(f5, 0.0f) * d5
                     + fmaxf(f6, 0.0f) * d6 + fmaxf(f7, 0.0f) * d7;
            ss[t * 11 + d] = sd;
        }
    }
    __syncthreads();

    // ---- Decoder/output: fully coalesced float4 y-load + out-store ----
    const float drb   = g_dec2[0];
    const float droot = g_dec2[1];
    const float4* yg = (const float4*)y + blk * 1280;
    float4* og = (float4*)out + blk * 1280;
#pragma unroll
    for (int p = 0; p < 10; p++) {
        const int n4 = t + p * 128;
        const int bl = n4 / 10, c = n4 % 10;
        const float sa = ss[bl * 11 + c];
        const float sb = ss[bl * 11 + (c == 9 ? 0 : c + 1)];
        const float4 yv = yg[n4];
        float4 o;
        o.x = sa + drb + yv.x * droot;          // m=0
        o.y = sa + sb + drb + yv.y * droot;     // m=1
        o.z = sa + sb + drb + yv.z * droot;     // m=2
        o.w = sb + drb + yv.w * droot;          // m=3
        og[n4] = o;
    }
}

extern "C" void kernel_launch(void* const* d_in, const int* in_sizes, int n_in,
                              void* d_out, int out_size) {
    const float* x     = (const float*)d_in[0];
    const float* z     = (const float*)d_in[1];
    const float* y     = (const float*)d_in[2];
    const float* erw   = (const float*)d_in[3];
    const float* erb   = (const float*)d_in[4];
    const float* erow  = (const float*)d_in[5];
    const float* prw   = (const float*)d_in[6];
    const float* prb   = (const float*)d_in[7];
    const float* prow  = (const float*)d_in[8];
    const float* drw   = (const float*)d_in[9];
    const float* drb   = (const float*)d_in[10];
    const float* droot = (const float*)d_in[11];

    const int B = in_sizes[0] / 40;       // 524288
    const int blocks = B / 128;           // 4096

    cudaFuncSetAttribute(gnn_kernel, cudaFuncAttributeMaxDynamicSharedMemorySize, SMEM_BYTES);
    prep_kernel<<<1, 32>>>(erw, erb, erow, prw, prb, prow, drw, drb, droot);
    gnn_kernel<<<blocks, 128, SMEM_BYTES>>>(x, z, y, (float*)d_out);
}

// round 4
// speedup vs baseline: 1.1354x; 1.1354x over previous
#include <cuda_runtime.h>

// HN=10, ND=40, HF=8, STRIDE=3, ESTRIDE=3 (fixed by reference)
// A_ENC: agg[j] = sum x[4j-3 .. 4j+2 mod 40]
// A_PRED: agg2[d] = z1[d] + w*(z1[d-1]+z1[d+1]), w = exp(-1/9)
// A_DEC per grid i (m=i%4): m0:s[c]; m1:s[c]+s[c+1]; m2:s[c]+s[c+1]; m3:s[c+1]  (c=i/4, wrap mod 10)

typedef unsigned long long u64;

__device__ __forceinline__ u64 pk2(float a, float b) {
    u64 r; asm("mov.b64 %0, {%1, %2};" : "=l"(r) : "f"(a), "f"(b)); return r;
}
__device__ __forceinline__ void upk2(u64 v, float& a, float& b) {
    asm("mov.b64 {%0, %1}, %2;" : "=f"(a), "=f"(b) : "l"(v));
}
__device__ __forceinline__ u64 ffma2(u64 a, u64 b, u64 c) {
    u64 d; asm("fma.rn.f32x2 %0, %1, %2, %3;" : "=l"(d) : "l"(a), "l"(b), "l"(c)); return d;
}

// Packed weights written by prep_kernel (deterministic each launch)
__device__ u64 g_encW[8][4];   // [g][f2] = (enc_root_w[2f2][g], enc_root_w[2f2+1][g])
__device__ u64 g_encRW[4];     // enc_rel_w pairs
__device__ u64 g_encB[4];      // enc_rel_b pairs
__device__ u64 g_W1[8][4];     // (pred_rel_w + pred_root_w) pairs
__device__ u64 g_W2[8][4];     // (exp(-1/9) * pred_rel_w) pairs
__device__ u64 g_predB[4];     // pred_rel_b pairs
__device__ float g_drw[8];     // dec_rel_w
__device__ float g_dec2[2];    // dec_rel_b, dec_root_w

__global__ void prep_kernel(const float* __restrict__ erw, const float* __restrict__ erb,
                            const float* __restrict__ erow,
                            const float* __restrict__ prw, const float* __restrict__ prb,
                            const float* __restrict__ prow,
                            const float* __restrict__ drw, const float* __restrict__ drb,
                            const float* __restrict__ droot) {
    const int t = threadIdx.x;
    const float wE = expf(-1.0f / 9.0f);
    if (t < 32) {
        const int g = t & 7, f2 = t >> 3;
        const int i0 = (2 * f2) * 8 + g;
        const int i1 = (2 * f2 + 1) * 8 + g;
        g_encW[g][f2] = pk2(erow[i0], erow[i1]);
        g_W1[g][f2]   = pk2(prw[i0] + prow[i0], prw[i1] + prow[i1]);
        g_W2[g][f2]   = pk2(wE * prw[i0], wE * prw[i1]);
    }
    if (t < 4) {
        g_encRW[t] = pk2(erw[2 * t], erw[2 * t + 1]);
        g_encB[t]  = pk2(erb[2 * t], erb[2 * t + 1]);
        g_predB[t] = pk2(prb[2 * t], prb[2 * t + 1]);
    }
    if (t < 8) g_drw[t] = drw[t];
    if (t == 0) { g_dec2[0] = drb[0]; g_dec2[1] = droot[0]; }
}

// Shared: buf float4[128*21] (x transiently as [128][11], then z/z1) = 43008B
//         ss float[128*11] = 5632B.  Total 48640B -> 3 blocks/SM at 170 regs.
#define ZROW 21
#define SMEM_BYTES (128 * ZROW * 16 + 128 * 11 * 4)

__global__ __launch_bounds__(128, 3)
void gnn_kernel(const float* __restrict__ x, const float* __restrict__ z,
                const float* __restrict__ y, float* __restrict__ out) {
    extern __shared__ float4 sm4[];
    float4* buf = sm4;
    float*  ss  = (float*)(sm4 + 128 * ZROW);

    const int t = threadIdx.x;
    const int blk = blockIdx.x;

    // ---- Phase 1: stage x coalesced into [128][11] float4 (stride 11: conflict-free) ----
    const float4* xg = (const float4*)x + blk * 1280;
#pragma unroll
    for (int k = 0; k < 10; k++) {
        const int i4 = t + k * 128;
        buf[(i4 / 10) * 11 + (i4 % 10)] = xg[i4];
    }
    __syncthreads();

    // ---- Phase 2: encoder ring aggregation, directly from float4 chunks ----
    // agg[j] = (chunk[j-1].y + .z + .w) + (chunk[j].x + .y + .z)
    float t1[10], t2[10];
#pragma unroll
    for (int c = 0; c < 10; c++) {
        const float4 v = buf[t * 11 + c];
        t1[c] = v.y + v.z + v.w;
        t2[c] = v.x + v.y + v.z;
    }
    float agg[10];
#pragma unroll
    for (int j = 0; j < 10; j++) agg[j] = t1[(j + 9) % 10] + t2[j];
    __syncthreads();   // x reads done before z overwrites buf

    // ---- Phase 3: stage z coalesced into [128][21] float4 (slots 0..19, no swizzle) ----
    const float4* zg = (const float4*)z + blk * 2560;
#pragma unroll
    for (int k = 0; k < 20; k++) {
        const int i4 = t + k * 128;
        buf[(i4 / 20) * ZROW + (i4 % 20)] = zg[i4];
    }
    __syncthreads();

    float4* row = buf + t * ZROW;   // this thread's private row (node j at slots 2j, 2j+1)

    // ======== Stage A: z1[j] = relu(agg[j]*erw + erb + z[j]·erow^T), node halves ========
#pragma unroll
    for (int jh = 0; jh < 2; jh++) {
        const int j0 = jh * 5;
        u64 acc[20];
        {
            const u64 rw0 = g_encRW[0], rw1 = g_encRW[1], rw2 = g_encRW[2], rw3 = g_encRW[3];
            const u64 b0 = g_encB[0], b1 = g_encB[1], b2 = g_encB[2], b3 = g_encB[3];
#pragma unroll
            for (int j5 = 0; j5 < 5; j5++) {
                const u64 ab = pk2(agg[j0 + j5], agg[j0 + j5]);
                acc[j5 * 4 + 0] = ffma2(ab, rw0, b0);
                acc[j5 * 4 + 1] = ffma2(ab, rw1, b1);
                acc[j5 * 4 + 2] = ffma2(ab, rw2, b2);
                acc[j5 * 4 + 3] = ffma2(ab, rw3, b3);
            }
        }
#pragma unroll 1
        for (int gh = 0; gh < 2; gh++) {
            u64 w[4][4];
#pragma unroll
            for (int gw = 0; gw < 4; gw++)
#pragma unroll
                for (int f2 = 0; f2 < 4; f2++) w[gw][f2] = g_encW[4 * gh + gw][f2];
#pragma unroll
            for (int j5 = 0; j5 < 5; j5++) {
                const float4 zv = row[2 * (j0 + j5) + gh];
                const float zs[4] = {zv.x, zv.y, zv.z, zv.w};
#pragma unroll
                for (int gw = 0; gw < 4; gw++) {
                    const u64 zb = pk2(zs[gw], zs[gw]);
                    acc[j5 * 4 + 0] = ffma2(zb, w[gw][0], acc[j5 * 4 + 0]);
                    acc[j5 * 4 + 1] = ffma2(zb, w[gw][1], acc[j5 * 4 + 1]);
                    acc[j5 * 4 + 2] = ffma2(zb, w[gw][2], acc[j5 * 4 + 2]);
                    acc[j5 * 4 + 3] = ffma2(zb, w[gw][3], acc[j5 * 4 + 3]);
                }
            }
        }
        // relu, write z1 back in place (own row only, no sync needed)
#pragma unroll
        for (int j5 = 0; j5 < 5; j5++) {
            float f0, f1, f2v, f3, f4v, f5, f6, f7;
            upk2(acc[j5 * 4 + 0], f0, f1);
            upk2(acc[j5 * 4 + 1], f2v, f3);
            upk2(acc[j5 * 4 + 2], f4v, f5);
            upk2(acc[j5 * 4 + 3], f6, f7);
            float4 lo, hi;
            lo.x = fmaxf(f0, 0.0f);  lo.y = fmaxf(f1, 0.0f);
            lo.z = fmaxf(f2v, 0.0f); lo.w = fmaxf(f3, 0.0f);
            hi.x = fmaxf(f4v, 0.0f); hi.y = fmaxf(f5, 0.0f);
            hi.z = fmaxf(f6, 0.0f);  hi.w = fmaxf(f7, 0.0f);
            row[2 * (j0 + j5)]     = lo;
            row[2 * (j0 + j5) + 1] = hi;
        }
    }

    // ======== Stage B: z2[d] = relu(z1[d]@W1^T + (z1[d-1]+z1[d+1])@W2^T + prb) ========
    //          s[d] = z2[d]·drw  — node halves, g halves rolled
    const float d0w = g_drw[0], d1w = g_drw[1], d2w = g_drw[2], d3w = g_drw[3];
    const float d4w = g_drw[4], d5w = g_drw[5], d6w = g_drw[6], d7w = g_drw[7];
#pragma unroll
    for (int dh = 0; dh < 2; dh++) {
        const int d0 = dh * 5;
        u64 acc[20];
        {
            const u64 pb0 = g_predB[0], pb1 = g_predB[1], pb2 = g_predB[2], pb3 = g_predB[3];
#pragma unroll
            for (int d5 = 0; d5 < 5; d5++) {
                acc[d5 * 4 + 0] = pb0; acc[d5 * 4 + 1] = pb1;
                acc[d5 * 4 + 2] = pb2; acc[d5 * 4 + 3] = pb3;
            }
        }
#pragma unroll 1
        for (int gh = 0; gh < 2; gh++) {
            u64 a[4][4], c[4][4];
#pragma unroll
            for (int gw = 0; gw < 4; gw++)
#pragma unroll
                for (int f2 = 0; f2 < 4; f2++) {
                    a[gw][f2] = g_W1[4 * gh + gw][f2];
                    c[gw][f2] = g_W2[4 * gh + gw][f2];
                }
            // z1 rows for nodes d0-1 .. d0+5 (7 rows, ring-wrapped)
            float4 zr[7];
#pragma unroll
            for (int k = 0; k < 7; k++)
                zr[k] = row[2 * ((d0 + k + 9) % 10) + gh];
#pragma unroll
            for (int d5 = 0; d5 < 5; d5++) {
                const float4 zd = zr[d5 + 1];
                float4 um;
                um.x = zr[d5].x + zr[d5 + 2].x;
                um.y = zr[d5].y + zr[d5 + 2].y;
                um.z = zr[d5].z + zr[d5 + 2].z;
                um.w = zr[d5].w + zr[d5 + 2].w;
                const float zs[4] = {zd.x, zd.y, zd.z, zd.w};
                const float us[4] = {um.x, um.y, um.z, um.w};
#pragma unroll
                for (int gw = 0; gw < 4; gw++) {
                    const u64 zb = pk2(zs[gw], zs[gw]);
                    const u64 ub = pk2(us[gw], us[gw]);
                    acc[d5 * 4 + 0] = ffma2(zb, a[gw][0], acc[d5 * 4 + 0]);
                    acc[d5 * 4 + 1] = ffma2(zb, a[gw][1], acc[d5 * 4 + 1]);
                    acc[d5 * 4 + 2] = ffma2(zb, a[gw][2], acc[d5 * 4 + 2]);
                    acc[d5 * 4 + 3] = ffma2(zb, a[gw][3], acc[d5 * 4 + 3]);
                    acc[d5 * 4 + 0] = ffma2(ub, c[gw][0], acc[d5 * 4 + 0]);
                    acc[d5 * 4 + 1] = ffma2(ub, c[gw][1], acc[d5 * 4 + 1]);
                    acc[d5 * 4 + 2] = ffma2(ub, c[gw][2], acc[d5 * 4 + 2]);
                    acc[d5 * 4 + 3] = ffma2(ub, c[gw][3], acc[d5 * 4 + 3]);
                }
            }
        }
        // relu + dot with dec_rel_w -> s[d]
#pragma unroll
        for (int d5 = 0; d5 < 5; d5++) {
            float f0, f1, f2v, f3, f4v, f5, f6, f7;
            upk2(acc[d5 * 4 + 0], f0, f1);
            upk2(acc[d5 * 4 + 1], f2v, f3);
            upk2(acc[d5 * 4 + 2], f4v, f5);
            upk2(acc[d5 * 4 + 3], f6, f7);
            const float sd = fmaxf(f0, 0.0f) * d0w + fmaxf(f1, 0.0f) * d1w
                           + fmaxf(f2v, 0.0f) * d2w + fmaxf(f3, 0.0f) * d3w
                           + fmaxf(f4v, 0.0f) * d4w + fmaxf(f5, 0.0f) * d5w
                           + fmaxf(f6, 0.0f) * d6w + fmaxf(f7, 0.0f) * d7w;
            ss[t * 11 + d0 + d5] = sd;
        }
    }
    __syncthreads();

    // ---- Decoder/output: fully coalesced float4 y-load + out-store ----
    const float drb   = g_dec2[0];
    const float droot = g_dec2[1];
    const float4* yg = (const float4*)y + blk * 1280;
    float4* og = (float4*)out + blk * 1280;
#pragma unroll
    for (int p = 0; p < 10; p++) {
        const int n4 = t + p * 128;
        const int bl = n4 / 10, c = n4 % 10;
        const float sa = ss[bl * 11 + c];
        const float sb = ss[bl * 11 + (c == 9 ? 0 : c + 1)];
        const float4 yv = yg[n4];
        float4 o;
        o.x = sa + drb + yv.x * droot;          // m=0
        o.y = sa + sb + drb + yv.y * droot;     // m=1
        o.z = sa + sb + drb + yv.z * droot;     // m=2
        o.w = sb + drb + yv.w * droot;          // m=3
        og[n4] = o;
    }
}

extern "C" void kernel_launch(void* const* d_in, const int* in_sizes, int n_in,
                              void* d_out, int out_size) {
    const float* x     = (const float*)d_in[0];
    const float* z     = (const float*)d_in[1];
    const float* y     = (const float*)d_in[2];
    const float* erw   = (const float*)d_in[3];
    const float* erb   = (const float*)d_in[4];
    const float* erow  = (const float*)d_in[5];
    const float* prw   = (const float*)d_in[6];
    const float* prb   = (const float*)d_in[7];
    const float* prow  = (const float*)d_in[8];
    const float* drw   = (const float*)d_in[9];
    const float* drb   = (const float*)d_in[10];
    const float* droot = (const float*)d_in[11];

    const int B = in_sizes[0] / 40;       // 524288
    const int blocks = B / 128;           // 4096

    cudaFuncSetAttribute(gnn_kernel, cudaFuncAttributeMaxDynamicSharedMemorySize, SMEM_BYTES);
    prep_kernel<<<1, 32>>>(erw, erb, erow, prw, prb, prow, drw, drb, droot);
    gnn_kernel<<<blocks, 128, SMEM_BYTES>>>(x, z, y, (float*)d_out);
}

// round 5
// speedup vs baseline: 1.3344x; 1.1753x over previous
#include <cuda_runtime.h>

// HN=10, ND=40, HF=8 (fixed). A_ENC: agg[j]=sum x[4j-3..4j+2 mod 40].
// A_PRED: agg2[d]=z1[d]+w*(z1[d-1]+z1[d+1]), w=exp(-1/9).
// A_DEC per grid i (m=i%4): m0:s[c]; m1,m2:s[c]+s[c+1]; m3:s[c+1]  (c=i/4, wrap mod 10)

typedef unsigned long long u64;

__device__ __forceinline__ u64 pk2(float a, float b) {
    u64 r; asm("mov.b64 %0, {%1, %2};" : "=l"(r) : "f"(a), "f"(b)); return r;
}
__device__ __forceinline__ void upk2(u64 v, float& a, float& b) {
    asm("mov.b64 {%0, %1}, %2;" : "=f"(a), "=f"(b) : "l"(v));
}
__device__ __forceinline__ u64 ffma2(u64 a, u64 b, u64 c) {
    u64 d; asm("fma.rn.f32x2 %0, %1, %2, %3;" : "=l"(d) : "l"(a), "l"(b), "l"(c)); return d;
}
__device__ __forceinline__ u64 add2(u64 a, u64 b) {
    u64 d; asm("add.rn.f32x2 %0, %1, %2;" : "=l"(d) : "l"(a), "l"(b)); return d;
}

struct CW {
    u64 encW[8][4];   // [g][f2] = (enc_root_w[2f2][g], enc_root_w[2f2+1][g])
    u64 encRW[4];     // enc_rel_w pairs
    u64 encB[4];      // enc_rel_b pairs
    u64 W1[8][4];     // (pred_rel_w + pred_root_w) pairs
    u64 W2[8][4];     // (exp(-1/9) * pred_rel_w) pairs
    u64 predB[4];     // pred_rel_b pairs
    float drw[8];     // dec_rel_w
    float dec2[2];    // dec_rel_b, dec_root_w
};
__constant__ CW c_w;
__device__ CW g_stage;

__global__ void prep_kernel(const float* __restrict__ erw, const float* __restrict__ erb,
                            const float* __restrict__ erow,
                            const float* __restrict__ prw, const float* __restrict__ prb,
                            const float* __restrict__ prow,
                            const float* __restrict__ drw, const float* __restrict__ drb,
                            const float* __restrict__ droot) {
    const int t = threadIdx.x;
    const float wE = expf(-1.0f / 9.0f);
    if (t < 32) {
        const int g = t & 7, f2 = t >> 3;
        const int i0 = (2 * f2) * 8 + g;
        const int i1 = (2 * f2 + 1) * 8 + g;
        g_stage.encW[g][f2] = pk2(erow[i0], erow[i1]);
        g_stage.W1[g][f2]   = pk2(prw[i0] + prow[i0], prw[i1] + prow[i1]);
        g_stage.W2[g][f2]   = pk2(wE * prw[i0], wE * prw[i1]);
    }
    if (t < 4) {
        g_stage.encRW[t] = pk2(erw[2 * t], erw[2 * t + 1]);
        g_stage.encB[t]  = pk2(erb[2 * t], erb[2 * t + 1]);
        g_stage.predB[t] = pk2(prb[2 * t], prb[2 * t + 1]);
    }
    if (t < 8) g_stage.drw[t] = drw[t];
    if (t == 0) { g_stage.dec2[0] = drb[0]; g_stage.dec2[1] = droot[0]; }
}

// Shared: buf float4[128*21] (x transient as [128][11] f4, then z, then z1 as u64
// rows of stride 41) = 43008B; ss float[128*11] = 5632B. Total 48640B -> 4 blocks/SM.
#define ZROW 21
#define SMEM_BYTES (128 * ZROW * 16 + 128 * 11 * 4)

__global__ __launch_bounds__(128, 4)
void gnn_kernel(const float* __restrict__ x, const float* __restrict__ z,
                const float* __restrict__ y, float* __restrict__ out) {
    extern __shared__ float4 sm4[];
    float4* buf = sm4;
    float*  ss  = (float*)(sm4 + 128 * ZROW);
    u64*    z1b = (u64*)sm4;            // reuses buf; row stride 41 u64 (conflict-free LDS.64)

    const int t = threadIdx.x;
    const int blk = blockIdx.x;

    // ---- Phase 1: stage x coalesced into [128][11] float4 ----
    const float4* xg = (const float4*)x + (long long)blk * 1280;
#pragma unroll
    for (int k = 0; k < 10; k++) {
        const int i4 = t + k * 128;
        buf[(i4 / 10) * 11 + (i4 % 10)] = xg[i4];
    }
    __syncthreads();

    // ---- Phase 2: encoder ring aggregation ----
    float t1[10], t2[10];
#pragma unroll
    for (int c = 0; c < 10; c++) {
        const float4 v = buf[t * 11 + c];
        t1[c] = v.y + v.z + v.w;
        t2[c] = v.x + v.y + v.z;
    }
    float agg[10];
#pragma unroll
    for (int j = 0; j < 10; j++) agg[j] = t1[(j + 9) % 10] + t2[j];
    __syncthreads();

    // ---- Phase 3: stage z coalesced into [128][21] float4 ----
    const float4* zg = (const float4*)z + (long long)blk * 2560;
#pragma unroll
    for (int k = 0; k < 20; k++) {
        const int i4 = t + k * 128;
        buf[(i4 / 20) * ZROW + (i4 % 20)] = zg[i4];
    }
    __syncthreads();

    const float4* row = buf + t * ZROW;

    // ======== Stage A: zz[4j+f2] = (z1[j][2f2], z1[j][2f2+1]) pre-relu ========
    u64 zz[40];
#pragma unroll
    for (int j = 0; j < 10; j++) {
        const u64 ab = pk2(agg[j], agg[j]);
#pragma unroll
        for (int f2 = 0; f2 < 4; f2++)
            zz[4 * j + f2] = ffma2(ab, c_w.encRW[f2], c_w.encB[f2]);
    }
#pragma unroll 1
    for (int gh = 0; gh < 2; gh++) {
        u64 w[4][4];
#pragma unroll
        for (int gw = 0; gw < 4; gw++)
#pragma unroll
            for (int f2 = 0; f2 < 4; f2++) w[gw][f2] = c_w.encW[4 * gh + gw][f2];
#pragma unroll
        for (int j = 0; j < 10; j++) {
            const float4 zv = row[2 * j + gh];
            const float zsc[4] = {zv.x, zv.y, zv.z, zv.w};
#pragma unroll
            for (int gw = 0; gw < 4; gw++) {
                const u64 zb = pk2(zsc[gw], zsc[gw]);
#pragma unroll
                for (int f2 = 0; f2 < 4; f2++)
                    zz[4 * j + f2] = ffma2(zb, w[gw][f2], zz[4 * j + f2]);
            }
        }
    }
    __syncthreads();   // every thread done reading z before z1 overwrites buf

    // relu + store z1 as packed b64 pairs (own row only; no barrier needed before reads)
    u64* myz1 = z1b + t * 41;
#pragma unroll
    for (int i = 0; i < 40; i++) {
        float a, b; upk2(zz[i], a, b);
        myz1[i] = pk2(fmaxf(a, 0.0f), fmaxf(b, 0.0f));
    }

    // ======== Stage B: z2[d] = relu(z1[d]@W1^T + (z1[d-1]+z1[d+1])@W2^T + prb) ========
    //          s[d] = z2[d]·drw
#pragma unroll
    for (int dh = 0; dh < 2; dh++) {
        u64 acc[20];
#pragma unroll
        for (int d5 = 0; d5 < 5; d5++)
#pragma unroll
            for (int f2 = 0; f2 < 4; f2++) acc[4 * d5 + f2] = c_w.predB[f2];

#pragma unroll 1
        for (int p = 0; p < 4; p++) {       // g-pair (2p, 2p+1)
            u64 w1lo[4], w1hi[4], w2lo[4], w2hi[4];
#pragma unroll
            for (int f2 = 0; f2 < 4; f2++) {
                w1lo[f2] = c_w.W1[2 * p][f2];
                w1hi[f2] = c_w.W1[2 * p + 1][f2];
                w2lo[f2] = c_w.W2[2 * p][f2];
                w2hi[f2] = c_w.W2[2 * p + 1][f2];
            }
            u64 zr[7];
#pragma unroll
            for (int k = 0; k < 7; k++)
                zr[k] = myz1[4 * ((dh * 5 + k + 9) % 10) + p];
#pragma unroll
            for (int d5 = 0; d5 < 5; d5++) {
                const u64 zd = zr[d5 + 1];
                const u64 up = add2(zr[d5], zr[d5 + 2]);
                float zl, zh, ul, uh;
                upk2(zd, zl, zh); upk2(up, ul, uh);
                const u64 bzl = pk2(zl, zl), bzh = pk2(zh, zh);
                const u64 bul = pk2(ul, ul), buh = pk2(uh, uh);
#pragma unroll
                for (int f2 = 0; f2 < 4; f2++) {
                    u64 a = acc[4 * d5 + f2];
                    a = ffma2(bzl, w1lo[f2], a);
                    a = ffma2(bzh, w1hi[f2], a);
                    a = ffma2(bul, w2lo[f2], a);
                    a = ffma2(buh, w2hi[f2], a);
                    acc[4 * d5 + f2] = a;
                }
            }
        }
        // relu + dot with dec_rel_w -> s[d]  (ss is a separate region: no race)
#pragma unroll
        for (int d5 = 0; d5 < 5; d5++) {
            float f0, f1, f2v, f3, f4v, f5, f6, f7;
            upk2(acc[4 * d5 + 0], f0, f1);
            upk2(acc[4 * d5 + 1], f2v, f3);
            upk2(acc[4 * d5 + 2], f4v, f5);
            upk2(acc[4 * d5 + 3], f6, f7);
            const float sd = fmaxf(f0, 0.0f) * c_w.drw[0] + fmaxf(f1, 0.0f) * c_w.drw[1]
                           + fmaxf(f2v, 0.0f) * c_w.drw[2] + fmaxf(f3, 0.0f) * c_w.drw[3]
                           + fmaxf(f4v, 0.0f) * c_w.drw[4] + fmaxf(f5, 0.0f) * c_w.drw[5]
                           + fmaxf(f6, 0.0f) * c_w.drw[6] + fmaxf(f7, 0.0f) * c_w.drw[7];
            ss[t * 11 + dh * 5 + d5] = sd;
        }
    }
    __syncthreads();

    // ---- Decoder/output: fully coalesced float4 y-load + out-store ----
    const float drb   = c_w.dec2[0];
    const float droot = c_w.dec2[1];
    const float4* yg = (const float4*)y + (long long)blk * 1280;
    float4* og = (float4*)out + (long long)blk * 1280;
#pragma unroll
    for (int p = 0; p < 10; p++) {
        const int n4 = t + p * 128;
        const int bl = n4 / 10, c = n4 % 10;
        const float sa = ss[bl * 11 + c];
        const float sb = ss[bl * 11 + (c == 9 ? 0 : c + 1)];
        const float4 yv = yg[n4];
        float4 o;
        o.x = sa + drb + yv.x * droot;          // m=0
        o.y = sa + sb + drb + yv.y * droot;     // m=1
        o.z = sa + sb + drb + yv.z * droot;     // m=2
        o.w = sb + drb + yv.w * droot;          // m=3
        og[n4] = o;
    }
}

extern "C" void kernel_launch(void* const* d_in, const int* in_sizes, int n_in,
                              void* d_out, int out_size) {
    const float* x     = (const float*)d_in[0];
    const float* z     = (const float*)d_in[1];
    const float* y     = (const float*)d_in[2];
    const float* erw   = (const float*)d_in[3];
    const float* erb   = (const float*)d_in[4];
    const float* erow  = (const float*)d_in[5];
    const float* prw   = (const float*)d_in[6];
    const float* prb   = (const float*)d_in[7];
    const float* prow  = (const float*)d_in[8];
    const float* drw   = (const float*)d_in[9];
    const float* drb   = (const float*)d_in[10];
    const float* droot = (const float*)d_in[11];

    const int B = in_sizes[0] / 40;       // 524288
    const int blocks = B / 128;           // 4096

    cudaFuncSetAttribute(gnn_kernel, cudaFuncAttributeMaxDynamicSharedMemorySize, SMEM_BYTES);

    prep_kernel<<<1, 32>>>(erw, erb, erow, prw, prb, prow, drw, drb, droot);

    void* stage_ptr = nullptr;
    cudaGetSymbolAddress(&stage_ptr, g_stage);
    cudaMemcpyToSymbolAsync(c_w, stage_ptr, sizeof(CW), 0, cudaMemcpyDeviceToDevice);

    gnn_kernel<<<blocks, 128, SMEM_BYTES>>>(x, z, y, (float*)d_out);
}